// round 1
// baseline (speedup 1.0000x reference)
#include <cuda_runtime.h>
#include <cstdint>

// Problem constants
#define HH   16
#define DD   64
#define BB   2
#define NN   1024
#define MM   2048
#define CC   1024
#define KVD  768
#define QK_SCALE 0.125f   // 64^-0.5

// Scratch (allocation-free: __device__ globals)
__device__ __align__(16) float g_qh[BB*HH*NN*DD];   // scaled Q, [b,h,n,d]
__device__ __align__(16) float g_k [BB*HH*MM*DD];   // K, [b,h,m,d]
__device__ __align__(16) float g_v [BB*HH*MM*DD];   // V, [b,h,m,d]
__device__ __align__(16) float g_x [BB*NN*CC];      // attn output, [b,n,h*D+d]
__device__ __align__(16) float g_maskbias[BB*MM];   // 0 or -1e30

// ---------------------------------------------------------------------------
// Mask prep: detect storage width of the bool padding_mask (u8 / i32 / f32)
// by byte-pattern sniffing the first 4096 bytes (safe for all three widths),
// then expand to float bias. One block.
// ---------------------------------------------------------------------------
__global__ void mask_prep(const unsigned char* __restrict__ raw)
{
    __shared__ int nzA, nzB;
    if (threadIdx.x == 0) { nzA = 0; nzB = 0; }
    __syncthreads();
    int la = 0, lb = 0;
    for (int i = threadIdx.x; i < BB*MM; i += blockDim.x) {
        unsigned char v = raw[i];
        int r = i & 3;
        if (v && r == 1) la++;
        if (v && r >= 2) lb++;
    }
    if (la) atomicAdd(&nzA, la);
    if (lb) atomicAdd(&nzB, lb);
    __syncthreads();
    // u8: nonzero bytes everywhere; f32(1.0f)=00 00 80 3F: nonzero only at r=2,3;
    // i32(1)=01 00 00 00: zero at r=1,2,3.
    int mode = (nzA > 0) ? 0 : ((nzB > 0) ? 1 : 2);
    for (int i = threadIdx.x; i < BB*MM; i += blockDim.x) {
        bool masked;
        if (mode == 0)      masked = raw[i] != 0;
        else if (mode == 1) masked = ((const float*)raw)[i] != 0.0f;
        else                masked = ((const int*)raw)[i] != 0;
        g_maskbias[i] = masked ? -1e30f : 0.0f;
    }
}

// ---------------------------------------------------------------------------
// Generic fp32 GEMM:  C[Mr,Nc] = A[Mr,K] @ B[Nc,K]^T  (both row-major)
// 128x128 block tile, BK=8, 8x8 per-thread microtile, 256 threads.
// EPI 0: scale by QK_SCALE, scatter to g_qh [b,h,n,d]
// EPI 1: scatter to g_k / g_v [b,h,m,d]
// EPI 2: add bias, write dense to Cout (A taken from g_x)
// ---------------------------------------------------------------------------
template<int EPI>
__global__ __launch_bounds__(256)
void gemm_tn(const float* __restrict__ A, const float* __restrict__ B,
             const float* __restrict__ bias, float* __restrict__ Cout,
             int K, int Nc)
{
    __shared__ float As[8][132];
    __shared__ float Bs[8][132];

    const int tid = threadIdx.x;
    const int tx  = tid & 15;
    const int ty  = tid >> 4;
    const int row0 = blockIdx.y * 128;
    const int col0 = blockIdx.x * 128;
    const int lr = tid >> 1;          // 0..127
    const int lc = (tid & 1) * 4;     // 0 or 4

    const float* Ap = (EPI == 2) ? g_x : A;
    const float* Aptr = Ap + (size_t)(row0 + lr) * K + lc;
    const float* Bptr = B  + (size_t)(col0 + lr) * K + lc;

    float acc[8][8];
    #pragma unroll
    for (int i = 0; i < 8; i++)
        #pragma unroll
        for (int j = 0; j < 8; j++) acc[i][j] = 0.0f;

    for (int kt = 0; kt < K; kt += 8) {
        float4 av = *(const float4*)(Aptr + kt);
        float4 bv = *(const float4*)(Bptr + kt);
        As[lc+0][lr] = av.x; As[lc+1][lr] = av.y;
        As[lc+2][lr] = av.z; As[lc+3][lr] = av.w;
        Bs[lc+0][lr] = bv.x; Bs[lc+1][lr] = bv.y;
        Bs[lc+2][lr] = bv.z; Bs[lc+3][lr] = bv.w;
        __syncthreads();
        #pragma unroll
        for (int k = 0; k < 8; k++) {
            float4 a0 = *(const float4*)&As[k][ty*4];
            float4 a1 = *(const float4*)&As[k][64 + ty*4];
            float4 b0 = *(const float4*)&Bs[k][tx*4];
            float4 b1 = *(const float4*)&Bs[k][64 + tx*4];
            float ar[8] = {a0.x,a0.y,a0.z,a0.w,a1.x,a1.y,a1.z,a1.w};
            float br[8] = {b0.x,b0.y,b0.z,b0.w,b1.x,b1.y,b1.z,b1.w};
            #pragma unroll
            for (int i = 0; i < 8; i++)
                #pragma unroll
                for (int j = 0; j < 8; j++)
                    acc[i][j] += ar[i] * br[j];
        }
        __syncthreads();
    }

    #pragma unroll
    for (int ii = 0; ii < 2; ii++)
    #pragma unroll
    for (int i = 0; i < 4; i++) {
        int r = row0 + ii*64 + ty*4 + i;
        #pragma unroll
        for (int jj = 0; jj < 2; jj++) {
            int c = col0 + jj*64 + tx*4;
            float4 v;
            v.x = acc[ii*4+i][jj*4+0];
            v.y = acc[ii*4+i][jj*4+1];
            v.z = acc[ii*4+i][jj*4+2];
            v.w = acc[ii*4+i][jj*4+3];
            if (EPI == 0) {
                v.x *= QK_SCALE; v.y *= QK_SCALE; v.z *= QK_SCALE; v.w *= QK_SCALE;
                int b = r >> 10, n = r & 1023, h = c >> 6, d = c & 63;
                *(float4*)&g_qh[(((size_t)(b*HH + h))*NN + n)*DD + d] = v;
            } else if (EPI == 1) {
                int b = r >> 11, m = r & 2047;
                int two = c >> 10, h = (c >> 6) & 15, d = c & 63;
                float* dst = two ? g_v : g_k;
                *(float4*)&dst[(((size_t)(b*HH + h))*MM + m)*DD + d] = v;
            } else {
                float4 bb = *(const float4*)&bias[c];
                v.x += bb.x; v.y += bb.y; v.z += bb.z; v.w += bb.w;
                *(float4*)&Cout[(size_t)r * Nc + c] = v;
            }
        }
    }
}

// ---------------------------------------------------------------------------
// Fused attention: per (b,h), 64-query-row blocks, stream keys in 64-row
// tiles; online softmax; alibi + padding bias fused; output to g_x.
// Block 256 threads (16x16), per-thread 4x4 microtiles.
// ---------------------------------------------------------------------------
#define QT  64
#define MT  64
#define SQK 68   // stride for q_t / k_t / v_s (float4-friendly)
#define SS  65   // stride for s_tile (kills bank conflicts on scalar column reads)
#define ATT_SMEM_FLOATS (3*64*SQK + 64*SS + 128)
#define ATT_SMEM_BYTES  (ATT_SMEM_FLOATS*4)

__global__ __launch_bounds__(256)
void attn_kernel(const float* __restrict__ alibi)
{
    extern __shared__ float sm[];
    float* q_t   = sm;                  // [d][r]
    float* k_t   = q_t + 64*SQK;        // [d][m]
    float* v_s   = k_t + 64*SQK;        // [m][d]
    float* s_t   = v_s + 64*SQK;        // [r][m], stride SS
    float* alpha = s_t + 64*SS;         // [64]
    float* linv  = alpha + 64;          // [64]

    const int tid = threadIdx.x;
    const int tx = tid & 15, ty = tid >> 4;
    const int bh = blockIdx.y;              // b*H + h
    const int n0 = blockIdx.x * QT;
    const int r0 = ty * 4, c0 = tx * 4;

    const float* qptr  = g_qh + ((size_t)bh * NN + n0) * DD;
    const float* kbase = g_k  + (size_t)bh * MM * DD;
    const float* vbase = g_v  + (size_t)bh * MM * DD;
    const float* abase = alibi + ((size_t)bh * NN + n0) * MM;
    const float* mrow  = g_maskbias + (size_t)(bh >> 4) * MM;

    // load Q tile transposed to [d][r]
    #pragma unroll
    for (int i = 0; i < 4; i++) {
        int s = tid + i*256;
        int r = s >> 4, dg = (s & 15) * 4;
        float4 qv = *(const float4*)(qptr + (size_t)r*DD + dg);
        q_t[(dg+0)*SQK + r] = qv.x;
        q_t[(dg+1)*SQK + r] = qv.y;
        q_t[(dg+2)*SQK + r] = qv.z;
        q_t[(dg+3)*SQK + r] = qv.w;
    }

    float acc[4][4];
    #pragma unroll
    for (int i = 0; i < 4; i++)
        #pragma unroll
        for (int j = 0; j < 4; j++) acc[i][j] = 0.0f;
    float m_loc = -1e30f, l_loc = 0.0f;

    for (int m0 = 0; m0 < MM; m0 += MT) {
        __syncthreads();  // previous tile fully consumed
        // load K tile transposed [d][m], V tile [m][d]
        #pragma unroll
        for (int i = 0; i < 4; i++) {
            int s = tid + i*256;
            int r = s >> 4, dg = (s & 15) * 4;
            float4 kv4 = *(const float4*)(kbase + (size_t)(m0 + r)*DD + dg);
            k_t[(dg+0)*SQK + r] = kv4.x;
            k_t[(dg+1)*SQK + r] = kv4.y;
            k_t[(dg+2)*SQK + r] = kv4.z;
            k_t[(dg+3)*SQK + r] = kv4.w;
            *(float4*)&v_s[r*SQK + dg] =
                *(const float4*)(vbase + (size_t)(m0 + r)*DD + dg);
        }
        __syncthreads();

        // S = Q @ K^T (q already scaled)
        float sreg[4][4];
        #pragma unroll
        for (int i = 0; i < 4; i++)
            #pragma unroll
            for (int j = 0; j < 4; j++) sreg[i][j] = 0.0f;
        #pragma unroll
        for (int kk = 0; kk < 64; kk++) {
            float4 qa = *(const float4*)&q_t[kk*SQK + r0];
            float4 ka = *(const float4*)&k_t[kk*SQK + c0];
            float qr[4] = {qa.x, qa.y, qa.z, qa.w};
            float kr[4] = {ka.x, ka.y, ka.z, ka.w};
            #pragma unroll
            for (int i = 0; i < 4; i++)
                #pragma unroll
                for (int j = 0; j < 4; j++)
                    sreg[i][j] += qr[i] * kr[j];
        }

        // + alibi + padding bias; stash to smem
        float4 mb = *(const float4*)&mrow[m0 + c0];
        #pragma unroll
        for (int i = 0; i < 4; i++) {
            float4 av = *(const float4*)&abase[(size_t)(r0 + i)*MM + m0 + c0];
            sreg[i][0] += av.x + mb.x;
            sreg[i][1] += av.y + mb.y;
            sreg[i][2] += av.z + mb.z;
            sreg[i][3] += av.w + mb.w;
            s_t[(r0+i)*SS + c0+0] = sreg[i][0];
            s_t[(r0+i)*SS + c0+1] = sreg[i][1];
            s_t[(r0+i)*SS + c0+2] = sreg[i][2];
            s_t[(r0+i)*SS + c0+3] = sreg[i][3];
        }
        __syncthreads();

        // online softmax per row (threads 0..63 own one row each)
        if (tid < 64) {
            float* row = s_t + tid * SS;
            float tmax = -1e30f;
            #pragma unroll 8
            for (int j = 0; j < 64; j++) tmax = fmaxf(tmax, row[j]);
            float mnew = fmaxf(m_loc, tmax);
            float a = __expf(m_loc - mnew);
            float sum = 0.0f;
            #pragma unroll 8
            for (int j = 0; j < 64; j++) {
                float p = __expf(row[j] - mnew);
                row[j] = p;
                sum += p;
            }
            l_loc = l_loc * a + sum;
            m_loc = mnew;
            alpha[tid] = a;
        }
        __syncthreads();

        // rescale accumulators, then acc += P @ V
        float al[4];
        #pragma unroll
        for (int i = 0; i < 4; i++) al[i] = alpha[r0 + i];
        #pragma unroll
        for (int i = 0; i < 4; i++)
            #pragma unroll
            for (int j = 0; j < 4; j++) acc[i][j] *= al[i];
        #pragma unroll 8
        for (int mm = 0; mm < 64; mm++) {
            float4 vv = *(const float4*)&v_s[mm*SQK + c0];
            #pragma unroll
            for (int i = 0; i < 4; i++) {
                float p = s_t[(r0+i)*SS + mm];
                acc[i][0] += p * vv.x;
                acc[i][1] += p * vv.y;
                acc[i][2] += p * vv.z;
                acc[i][3] += p * vv.w;
            }
        }
    }

    if (tid < 64) linv[tid] = 1.0f / l_loc;
    __syncthreads();

    // write normalized output to g_x [b, n, h*64 + d]
    const int h = bh & 15;
    float* xp = g_x + ((size_t)(bh >> 4) * NN + n0) * CC + h * DD;
    #pragma unroll
    for (int i = 0; i < 4; i++) {
        float li = linv[r0 + i];
        float4 o;
        o.x = acc[i][0] * li;
        o.y = acc[i][1] * li;
        o.z = acc[i][2] * li;
        o.w = acc[i][3] * li;
        *(float4*)&xp[(size_t)(r0 + i)*CC + c0] = o;
    }
}

// ---------------------------------------------------------------------------
extern "C" void kernel_launch(void* const* d_in, const int* in_sizes, int n_in,
                              void* d_out, int out_size)
{
    const float *q = nullptr, *kv = nullptr, *alibi = nullptr;
    const float *Wq = nullptr, *Wkv = nullptr, *Wproj = nullptr, *bproj = nullptr;
    const void  *maskp = nullptr;
    int wseen = 0;
    for (int i = 0; i < n_in; i++) {
        switch (in_sizes[i]) {
            case 2097152:  q     = (const float*)d_in[i]; break;           // (2,1024,1024)
            case 3145728:  kv    = (const float*)d_in[i]; break;           // (2,2048,768)
            case 67108864: alibi = (const float*)d_in[i]; break;           // (2,16,1024,2048)
            case 4096:     maskp = d_in[i]; break;                          // (2,2048) bool
            case 1572864:  Wkv   = (const float*)d_in[i]; break;           // (2048,768)
            case 1024:     bproj = (const float*)d_in[i]; break;           // (1024,)
            case 1048576:                                                   // Wq then Wproj
                if (wseen++ == 0) Wq = (const float*)d_in[i];
                else              Wproj = (const float*)d_in[i];
                break;
            default: break;
        }
    }
    float* out = (float*)d_out;
    (void)out_size;

    cudaFuncSetAttribute(attn_kernel,
                         cudaFuncAttributeMaxDynamicSharedMemorySize,
                         ATT_SMEM_BYTES);

    mask_prep<<<1, 256>>>((const unsigned char*)maskp);
    // Q projection: (2048,1024) = q @ Wq^T, scaled, scattered to [b,h,n,d]
    gemm_tn<0><<<dim3(CC/128, (BB*NN)/128), 256>>>(q,  Wq,  nullptr, nullptr, CC,  CC);
    // KV projection: (4096,2048) = kv @ Wkv^T, scattered to g_k / g_v
    gemm_tn<1><<<dim3((2*CC)/128, (BB*MM)/128), 256>>>(kv, Wkv, nullptr, nullptr, KVD, 2*CC);
    // Fused attention
    attn_kernel<<<dim3(NN/QT, BB*HH), 256, ATT_SMEM_BYTES>>>(alibi);
    // Output projection: out = g_x @ Wproj^T + bproj
    gemm_tn<2><<<dim3(CC/128, (BB*NN)/128), 256>>>(nullptr, Wproj, bproj, out, CC, CC);
}

// round 2
// speedup vs baseline: 1.0011x; 1.0011x over previous
#include <cuda_runtime.h>
#include <cstdint>

// Problem constants
#define HH   16
#define DD   64
#define BB   2
#define NN   1024
#define MM   2048
#define CC   1024
#define KVD  768
#define QK_SCALE 0.125f   // 64^-0.5

// Scratch (allocation-free: __device__ globals)
__device__ __align__(16) float g_qh[BB*HH*NN*DD];   // scaled Q, [b,h,n,d]
__device__ __align__(16) float g_k [BB*HH*MM*DD];   // K, [b,h,m,d]
__device__ __align__(16) float g_v [BB*HH*MM*DD];   // V, [b,h,m,d]
__device__ __align__(16) float g_x [BB*NN*CC];      // attn output, [b,n,h*D+d]
__device__ __align__(16) float g_maskbias[BB*MM];   // 0 or -1e30

// ---------------------------------------------------------------------------
// Mask prep: detect storage width of the bool padding_mask (u8 / i32 / f32)
// by byte-pattern sniffing the first 4096 bytes (safe for all three widths),
// then expand to float bias. One block.
// ---------------------------------------------------------------------------
__global__ void mask_prep(const unsigned char* __restrict__ raw)
{
    __shared__ int nzA, nzB;
    if (threadIdx.x == 0) { nzA = 0; nzB = 0; }
    __syncthreads();
    int la = 0, lb = 0;
    for (int i = threadIdx.x; i < BB*MM; i += blockDim.x) {
        unsigned char v = raw[i];
        int r = i & 3;
        if (v && r == 1) la++;
        if (v && r >= 2) lb++;
    }
    if (la) atomicAdd(&nzA, la);
    if (lb) atomicAdd(&nzB, lb);
    __syncthreads();
    // u8: nonzero bytes everywhere; f32(1.0f)=00 00 80 3F: nonzero only at r=2,3;
    // i32(1)=01 00 00 00: zero at r=1,2,3.
    int mode = (nzA > 0) ? 0 : ((nzB > 0) ? 1 : 2);
    for (int i = threadIdx.x; i < BB*MM; i += blockDim.x) {
        bool masked;
        if (mode == 0)      masked = raw[i] != 0;
        else if (mode == 1) masked = ((const float*)raw)[i] != 0.0f;
        else                masked = ((const int*)raw)[i] != 0;
        g_maskbias[i] = masked ? -1e30f : 0.0f;
    }
}

// ---------------------------------------------------------------------------
// Generic fp32 GEMM:  C[Mr,Nc] = A[Mr,K] @ B[Nc,K]^T  (both row-major)
// 128x128 block tile, BK=8, 8x8 per-thread microtile, 256 threads.
// EPI 0: scale by QK_SCALE, scatter to g_qh [b,h,n,d]
// EPI 1: scatter to g_k / g_v [b,h,m,d]
// EPI 2: add bias, write dense to Cout (A taken from g_x)
// ---------------------------------------------------------------------------
template<int EPI>
__global__ __launch_bounds__(256)
void gemm_tn(const float* __restrict__ A, const float* __restrict__ B,
             const float* __restrict__ bias, float* __restrict__ Cout,
             int K, int Nc)
{
    __shared__ float As[8][132];
    __shared__ float Bs[8][132];

    const int tid = threadIdx.x;
    const int tx  = tid & 15;
    const int ty  = tid >> 4;
    const int row0 = blockIdx.y * 128;
    const int col0 = blockIdx.x * 128;
    const int lr = tid >> 1;          // 0..127
    const int lc = (tid & 1) * 4;     // 0 or 4

    const float* Ap = (EPI == 2) ? g_x : A;
    const float* Aptr = Ap + (size_t)(row0 + lr) * K + lc;
    const float* Bptr = B  + (size_t)(col0 + lr) * K + lc;

    float acc[8][8];
    #pragma unroll
    for (int i = 0; i < 8; i++)
        #pragma unroll
        for (int j = 0; j < 8; j++) acc[i][j] = 0.0f;

    for (int kt = 0; kt < K; kt += 8) {
        float4 av = *(const float4*)(Aptr + kt);
        float4 bv = *(const float4*)(Bptr + kt);
        As[lc+0][lr] = av.x; As[lc+1][lr] = av.y;
        As[lc+2][lr] = av.z; As[lc+3][lr] = av.w;
        Bs[lc+0][lr] = bv.x; Bs[lc+1][lr] = bv.y;
        Bs[lc+2][lr] = bv.z; Bs[lc+3][lr] = bv.w;
        __syncthreads();
        #pragma unroll
        for (int k = 0; k < 8; k++) {
            float4 a0 = *(const float4*)&As[k][ty*4];
            float4 a1 = *(const float4*)&As[k][64 + ty*4];
            float4 b0 = *(const float4*)&Bs[k][tx*4];
            float4 b1 = *(const float4*)&Bs[k][64 + tx*4];
            float ar[8] = {a0.x,a0.y,a0.z,a0.w,a1.x,a1.y,a1.z,a1.w};
            float br[8] = {b0.x,b0.y,b0.z,b0.w,b1.x,b1.y,b1.z,b1.w};
            #pragma unroll
            for (int i = 0; i < 8; i++)
                #pragma unroll
                for (int j = 0; j < 8; j++)
                    acc[i][j] += ar[i] * br[j];
        }
        __syncthreads();
    }

    #pragma unroll
    for (int ii = 0; ii < 2; ii++)
    #pragma unroll
    for (int i = 0; i < 4; i++) {
        int r = row0 + ii*64 + ty*4 + i;
        #pragma unroll
        for (int jj = 0; jj < 2; jj++) {
            int c = col0 + jj*64 + tx*4;
            float4 v;
            v.x = acc[ii*4+i][jj*4+0];
            v.y = acc[ii*4+i][jj*4+1];
            v.z = acc[ii*4+i][jj*4+2];
            v.w = acc[ii*4+i][jj*4+3];
            if (EPI == 0) {
                v.x *= QK_SCALE; v.y *= QK_SCALE; v.z *= QK_SCALE; v.w *= QK_SCALE;
                int b = r >> 10, n = r & 1023, h = c >> 6, d = c & 63;
                *(float4*)&g_qh[(((size_t)(b*HH + h))*NN + n)*DD + d] = v;
            } else if (EPI == 1) {
                int b = r >> 11, m = r & 2047;
                int two = c >> 10, h = (c >> 6) & 15, d = c & 63;
                float* dst = two ? g_v : g_k;
                *(float4*)&dst[(((size_t)(b*HH + h))*MM + m)*DD + d] = v;
            } else {
                float4 bb = *(const float4*)&bias[c];
                v.x += bb.x; v.y += bb.y; v.z += bb.z; v.w += bb.w;
                *(float4*)&Cout[(size_t)r * Nc + c] = v;
            }
        }
    }
}

// ---------------------------------------------------------------------------
// Fused attention: per (b,h), 64-query-row blocks, stream keys in 64-row
// tiles; online softmax; alibi + padding bias fused; output to g_x.
// Block 256 threads (16x16), per-thread 4x4 microtiles.
// ---------------------------------------------------------------------------
#define QT  64
#define MT  64
#define SQK 68   // stride for q_t / k_t / v_s (float4-friendly)
#define SS  65   // stride for s_tile (kills bank conflicts on scalar column reads)
#define ATT_SMEM_FLOATS (3*64*SQK + 64*SS + 128)
#define ATT_SMEM_BYTES  (ATT_SMEM_FLOATS*4)

__global__ __launch_bounds__(256)
void attn_kernel(const float* __restrict__ alibi)
{
    extern __shared__ float sm[];
    float* q_t   = sm;                  // [d][r]
    float* k_t   = q_t + 64*SQK;        // [d][m]
    float* v_s   = k_t + 64*SQK;        // [m][d]
    float* s_t   = v_s + 64*SQK;        // [r][m], stride SS
    float* alpha = s_t + 64*SS;         // [64]
    float* linv  = alpha + 64;          // [64]

    const int tid = threadIdx.x;
    const int tx = tid & 15, ty = tid >> 4;
    const int bh = blockIdx.y;              // b*H + h
    const int n0 = blockIdx.x * QT;
    const int r0 = ty * 4, c0 = tx * 4;

    const float* qptr  = g_qh + ((size_t)bh * NN + n0) * DD;
    const float* kbase = g_k  + (size_t)bh * MM * DD;
    const float* vbase = g_v  + (size_t)bh * MM * DD;
    const float* abase = alibi + ((size_t)bh * NN + n0) * MM;
    const float* mrow  = g_maskbias + (size_t)(bh >> 4) * MM;

    // load Q tile transposed to [d][r]
    #pragma unroll
    for (int i = 0; i < 4; i++) {
        int s = tid + i*256;
        int r = s >> 4, dg = (s & 15) * 4;
        float4 qv = *(const float4*)(qptr + (size_t)r*DD + dg);
        q_t[(dg+0)*SQK + r] = qv.x;
        q_t[(dg+1)*SQK + r] = qv.y;
        q_t[(dg+2)*SQK + r] = qv.z;
        q_t[(dg+3)*SQK + r] = qv.w;
    }

    float acc[4][4];
    #pragma unroll
    for (int i = 0; i < 4; i++)
        #pragma unroll
        for (int j = 0; j < 4; j++) acc[i][j] = 0.0f;
    float m_loc = -1e30f, l_loc = 0.0f;

    for (int m0 = 0; m0 < MM; m0 += MT) {
        __syncthreads();  // previous tile fully consumed
        // load K tile transposed [d][m], V tile [m][d]
        #pragma unroll
        for (int i = 0; i < 4; i++) {
            int s = tid + i*256;
            int r = s >> 4, dg = (s & 15) * 4;
            float4 kv4 = *(const float4*)(kbase + (size_t)(m0 + r)*DD + dg);
            k_t[(dg+0)*SQK + r] = kv4.x;
            k_t[(dg+1)*SQK + r] = kv4.y;
            k_t[(dg+2)*SQK + r] = kv4.z;
            k_t[(dg+3)*SQK + r] = kv4.w;
            *(float4*)&v_s[r*SQK + dg] =
                *(const float4*)(vbase + (size_t)(m0 + r)*DD + dg);
        }
        __syncthreads();

        // S = Q @ K^T (q already scaled)
        float sreg[4][4];
        #pragma unroll
        for (int i = 0; i < 4; i++)
            #pragma unroll
            for (int j = 0; j < 4; j++) sreg[i][j] = 0.0f;
        #pragma unroll
        for (int kk = 0; kk < 64; kk++) {
            float4 qa = *(const float4*)&q_t[kk*SQK + r0];
            float4 ka = *(const float4*)&k_t[kk*SQK + c0];
            float qr[4] = {qa.x, qa.y, qa.z, qa.w};
            float kr[4] = {ka.x, ka.y, ka.z, ka.w};
            #pragma unroll
            for (int i = 0; i < 4; i++)
                #pragma unroll
                for (int j = 0; j < 4; j++)
                    sreg[i][j] += qr[i] * kr[j];
        }

        // + alibi + padding bias; stash to smem
        float4 mb = *(const float4*)&mrow[m0 + c0];
        #pragma unroll
        for (int i = 0; i < 4; i++) {
            float4 av = *(const float4*)&abase[(size_t)(r0 + i)*MM + m0 + c0];
            sreg[i][0] += av.x + mb.x;
            sreg[i][1] += av.y + mb.y;
            sreg[i][2] += av.z + mb.z;
            sreg[i][3] += av.w + mb.w;
            s_t[(r0+i)*SS + c0+0] = sreg[i][0];
            s_t[(r0+i)*SS + c0+1] = sreg[i][1];
            s_t[(r0+i)*SS + c0+2] = sreg[i][2];
            s_t[(r0+i)*SS + c0+3] = sreg[i][3];
        }
        __syncthreads();

        // online softmax per row (threads 0..63 own one row each)
        if (tid < 64) {
            float* row = s_t + tid * SS;
            float tmax = -1e30f;
            #pragma unroll 8
            for (int j = 0; j < 64; j++) tmax = fmaxf(tmax, row[j]);
            float mnew = fmaxf(m_loc, tmax);
            float a = __expf(m_loc - mnew);
            float sum = 0.0f;
            #pragma unroll 8
            for (int j = 0; j < 64; j++) {
                float p = __expf(row[j] - mnew);
                row[j] = p;
                sum += p;
            }
            l_loc = l_loc * a + sum;
            m_loc = mnew;
            alpha[tid] = a;
        }
        __syncthreads();

        // rescale accumulators, then acc += P @ V
        float al[4];
        #pragma unroll
        for (int i = 0; i < 4; i++) al[i] = alpha[r0 + i];
        #pragma unroll
        for (int i = 0; i < 4; i++)
            #pragma unroll
            for (int j = 0; j < 4; j++) acc[i][j] *= al[i];
        #pragma unroll 8
        for (int mm = 0; mm < 64; mm++) {
            float4 vv = *(const float4*)&v_s[mm*SQK + c0];
            #pragma unroll
            for (int i = 0; i < 4; i++) {
                float p = s_t[(r0+i)*SS + mm];
                acc[i][0] += p * vv.x;
                acc[i][1] += p * vv.y;
                acc[i][2] += p * vv.z;
                acc[i][3] += p * vv.w;
            }
        }
    }

    if (tid < 64) linv[tid] = 1.0f / l_loc;
    __syncthreads();

    // write normalized output to g_x [b, n, h*64 + d]
    const int h = bh & 15;
    float* xp = g_x + ((size_t)(bh >> 4) * NN + n0) * CC + h * DD;
    #pragma unroll
    for (int i = 0; i < 4; i++) {
        float li = linv[r0 + i];
        float4 o;
        o.x = acc[i][0] * li;
        o.y = acc[i][1] * li;
        o.z = acc[i][2] * li;
        o.w = acc[i][3] * li;
        *(float4*)&xp[(size_t)(r0 + i)*CC + c0] = o;
    }
}

// ---------------------------------------------------------------------------
extern "C" void kernel_launch(void* const* d_in, const int* in_sizes, int n_in,
                              void* d_out, int out_size)
{
    const float *q = nullptr, *kv = nullptr, *alibi = nullptr;
    const float *Wq = nullptr, *Wkv = nullptr, *Wproj = nullptr, *bproj = nullptr;
    const void  *maskp = nullptr;
    int wseen = 0;
    for (int i = 0; i < n_in; i++) {
        switch (in_sizes[i]) {
            case 2097152:  q     = (const float*)d_in[i]; break;           // (2,1024,1024)
            case 3145728:  kv    = (const float*)d_in[i]; break;           // (2,2048,768)
            case 67108864: alibi = (const float*)d_in[i]; break;           // (2,16,1024,2048)
            case 4096:     maskp = d_in[i]; break;                          // (2,2048) bool
            case 1572864:  Wkv   = (const float*)d_in[i]; break;           // (2048,768)
            case 1024:     bproj = (const float*)d_in[i]; break;           // (1024,)
            case 1048576:                                                   // Wq then Wproj
                if (wseen++ == 0) Wq = (const float*)d_in[i];
                else              Wproj = (const float*)d_in[i];
                break;
            default: break;
        }
    }
    float* out = (float*)d_out;
    (void)out_size;

    cudaFuncSetAttribute(attn_kernel,
                         cudaFuncAttributeMaxDynamicSharedMemorySize,
                         ATT_SMEM_BYTES);

    mask_prep<<<1, 256>>>((const unsigned char*)maskp);
    // Q projection: (2048,1024) = q @ Wq^T, scaled, scattered to [b,h,n,d]
    gemm_tn<0><<<dim3(CC/128, (BB*NN)/128), 256>>>(q,  Wq,  nullptr, nullptr, CC,  CC);
    // KV projection: (4096,2048) = kv @ Wkv^T, scattered to g_k / g_v
    gemm_tn<1><<<dim3((2*CC)/128, (BB*MM)/128), 256>>>(kv, Wkv, nullptr, nullptr, KVD, 2*CC);
    // Fused attention
    attn_kernel<<<dim3(NN/QT, BB*HH), 256, ATT_SMEM_BYTES>>>(alibi);
    // Output projection: out = g_x @ Wproj^T + bproj
    gemm_tn<2><<<dim3(CC/128, (BB*NN)/128), 256>>>(nullptr, Wproj, bproj, out, CC, CC);
}